// round 5
// baseline (speedup 1.0000x reference)
#include <cuda_runtime.h>
#include <math_constants.h>

// Problem constants
#define B_ 32
#define L_ 8192
#define C_ 256
#define S_ 8                  // L-splits
#define CHUNK_ (L_ / S_)      // 1024
#define MLP_ 16
#define TPB_ 64               // pass-1 block = 64 threads (one c-group)

// Partials: part4[(row*S + s)*2 + {0,1}], row = b*C + c.
// Slot: {mn0,mn1,mn2,mx0} {mx1,mx2,pad,pad}. 8192 rows * 256B = 2 MB.
__device__ float4 g_part4[(size_t)B_ * C_ * S_ * 2];

// Branchless insert of v into ascending triple (5 FMNMX)
__device__ __forceinline__ void bins_min(float v, float& mn0, float& mn1, float& mn2) {
    float h0 = fmaxf(mn0, v);
    mn0 = fminf(mn0, v);
    float h1 = fmaxf(mn1, h0);
    mn1 = fminf(mn1, h0);
    mn2 = fminf(mn2, h1);
}

// Branchless insert of v into descending triple (5 FMNMX)
__device__ __forceinline__ void bins_max(float v, float& mx0, float& mx1, float& mx2) {
    float l0 = fminf(mx0, v);
    mx0 = fmaxf(mx0, v);
    float l1 = fminf(mx1, l0);
    mx1 = fmaxf(mx1, l0);
    mx2 = fmaxf(mx2, l1);
}

// Pass 1: grid (C/64, S, B) = (4, 8, 32) = 1024 blocks x 64 threads.
// ~7 blocks/SM evenly, CHUNK=1024 per thread, 16 loads in flight.
// Pair min/max prefilter; triggered path is a flat branchless insert.
__global__ __launch_bounds__(TPB_) void kmm_partial(const float* __restrict__ x) {
    const int c = blockIdx.x * TPB_ + threadIdx.x;
    const int s = blockIdx.y;
    const int b = blockIdx.z;

    const float* __restrict__ p =
        x + ((size_t)b * L_ + (size_t)s * CHUNK_) * C_ + c;

    float mx0 = -CUDART_INF_F, mx1 = -CUDART_INF_F, mx2 = -CUDART_INF_F;
    float mn0 =  CUDART_INF_F, mn1 =  CUDART_INF_F, mn2 =  CUDART_INF_F;

    for (int l = 0; l < CHUNK_; l += MLP_) {
        float v[MLP_];
#pragma unroll
        for (int j = 0; j < MLP_; j++)
            v[j] = __ldg(p + (size_t)(l + j) * C_);
#pragma unroll
        for (int j = 0; j < MLP_; j += 2) {
            float lo = fminf(v[j], v[j + 1]);
            float hi = fmaxf(v[j], v[j + 1]);
            if (lo < mn2) {            // insert both, branchlessly
                bins_min(lo, mn0, mn1, mn2);
                bins_min(fminf(hi, mn2 + 0.0f) == hi ? hi : hi, mn0, mn1, mn2);
            }
            if (hi > mx2) {
                bins_max(hi, mx0, mx1, mx2);
                bins_max(lo, mx0, mx1, mx2);
            }
        }
    }

    const int row = b * C_ + c;
    float4* o4 = g_part4 + ((size_t)row * S_ + s) * 2;
    o4[0] = make_float4(mn0, mn1, mn2, mx0);
    o4[1] = make_float4(mx1, mx2, 0.f, 0.f);
}

// Pass 2: warp handles 4 rows; lane = (row&3)*8 + s. Each lane: 2x LDG.128,
// warp reads 1KB contiguous. 3 butterfly rounds merge 8 sorted triples.
__global__ __launch_bounds__(256) void kmm_reduce(float* __restrict__ out) {
    const int gtid = blockIdx.x * 256 + threadIdx.x;
    const int lane = gtid & 31;
    const int s    = lane & 7;           // partial index within row
    const int row  = gtid >> 3;          // 4 rows per warp

    const float4* r4 = g_part4 + ((size_t)row * S_ + s) * 2;
    float4 a  = __ldg(r4);
    float4 bq = __ldg(r4 + 1);

    float mn0 = a.x, mn1 = a.y, mn2 = a.z;
    float mx0 = a.w, mx1 = bq.x, mx2 = bq.y;

#pragma unroll
    for (int off = 4; off > 0; off >>= 1) {
        float b0 = __shfl_xor_sync(0xffffffffu, mn0, off);
        float b1 = __shfl_xor_sync(0xffffffffu, mn1, off);
        float b2 = __shfl_xor_sync(0xffffffffu, mn2, off);
        float c0 = __shfl_xor_sync(0xffffffffu, mx0, off);
        float c1 = __shfl_xor_sync(0xffffffffu, mx1, off);
        float c2 = __shfl_xor_sync(0xffffffffu, mx2, off);

        // merge two ascending triples -> 3 smallest of union
        {
            float x0 = fminf(mn0, b0), y0 = fmaxf(mn0, b0);
            float x1 = fminf(mn1, b1);
            float x2 = fminf(mn2, b2);
            mn0 = x0;
            mn1 = fminf(y0, x1);
            mn2 = fminf(x2, fmaxf(x1, y0));
        }
        // merge two descending triples -> 3 largest of union
        {
            float x0 = fmaxf(mx0, c0), y0 = fminf(mx0, c0);
            float x1 = fmaxf(mx1, c1);
            float x2 = fmaxf(mx2, c2);
            mx0 = x0;
            mx1 = fmaxf(y0, x1);
            mx2 = fmaxf(x2, fminf(x1, y0));
        }
    }

    if (s == 0) {
        float* r = out + (size_t)row * 6;
        r[0] = mn0; r[1] = mn1; r[2] = mn2;
        r[3] = mx0; r[4] = mx1; r[5] = mx2;
    }
}

extern "C" void kernel_launch(void* const* d_in, const int* in_sizes, int n_in,
                              void* d_out, int out_size) {
    const float* x = (const float*)d_in[0];
    float* out = (float*)d_out;

    dim3 grid1(C_ / TPB_, S_, B_);
    kmm_partial<<<grid1, TPB_>>>(x);

    // 8192 rows * 8 lanes = 65536 threads = 256 blocks x 256
    kmm_reduce<<<(B_ * C_ * S_) / 256, 256>>>(out);
}

// round 6
// speedup vs baseline: 1.7671x; 1.7671x over previous
#include <cuda_runtime.h>
#include <math_constants.h>

// Problem constants
#define B_ 32
#define L_ 8192
#define C_ 256
#define S_ 32                 // L-splits == warp size (reduce: lane = s)
#define CHUNK_ (L_ / S_)      // 256
#define MLP_ 8

// Partials, padded row-major: part4[row][s*2 + {0,1}], row = b*C + c.
// Slot layout: {mn0,mn1,mn2,mx0} {mx1,mx2,pad,pad}. 8192 rows * 1KB = 8MB.
__device__ float4 g_part4[(size_t)B_ * C_ * S_ * 2];

// Pass 1: grid (S, B) = 1024 blocks x 256 threads = one full resident wave
// at 8 blocks/SM (64 warps/SM). Thread c scans CHUNK_ l-values.
// Fully branchless: each pair (lo<=hi) is merged into the sorted triples
// with a 6-FMNMX merge network per side (3+3 network with one input = inf).
__global__ __launch_bounds__(C_, 8) void kmm_partial(const float* __restrict__ x) {
    const int c = threadIdx.x;
    const int s = blockIdx.x;
    const int b = blockIdx.y;

    const float* __restrict__ p =
        x + ((size_t)b * L_ + (size_t)s * CHUNK_) * C_ + c;

    float mx0 = -CUDART_INF_F, mx1 = -CUDART_INF_F, mx2 = -CUDART_INF_F;
    float mn0 =  CUDART_INF_F, mn1 =  CUDART_INF_F, mn2 =  CUDART_INF_F;

    for (int l = 0; l < CHUNK_; l += MLP_) {
        float v[MLP_];
#pragma unroll
        for (int j = 0; j < MLP_; j++)
            v[j] = __ldg(p + (size_t)(l + j) * C_);
#pragma unroll
        for (int j = 0; j < MLP_; j += 2) {
            const float lo = fminf(v[j], v[j + 1]);
            const float hi = fmaxf(v[j], v[j + 1]);

            // merge ascending (mn0,mn1,mn2) with ascending (lo,hi,+inf):
            // keep 3 smallest of union. 6 FMNMX, branchless.
            {
                float x0 = fminf(mn0, lo);
                float y0 = fmaxf(mn0, lo);
                float x1 = fminf(mn1, hi);
                float t  = fmaxf(x1, y0);
                mn0 = x0;
                mn1 = fminf(y0, x1);
                mn2 = fminf(mn2, t);
            }
            // merge descending (mx0,mx1,mx2) with descending (hi,lo,-inf):
            // keep 3 largest of union. 6 FMNMX, branchless.
            {
                float x0 = fmaxf(mx0, hi);
                float y0 = fminf(mx0, hi);
                float x1 = fmaxf(mx1, lo);
                float t  = fminf(x1, y0);
                mx0 = x0;
                mx1 = fmaxf(y0, x1);
                mx2 = fmaxf(mx2, t);
            }
        }
    }

    float4* o4 = g_part4 + ((size_t)(b * C_ + c) * S_ + s) * 2;
    o4[0] = make_float4(mn0, mn1, mn2, mx0);
    o4[1] = make_float4(mx1, mx2, 0.f, 0.f);
}

// Pass 2: one warp per (b,c) row, lane = s. Each lane: 2x LDG.128, warp reads
// 1KB contiguous (fully coalesced). Butterfly shfl merge of 32 sorted triples.
__global__ __launch_bounds__(256) void kmm_reduce(float* __restrict__ out) {
    const int gtid = blockIdx.x * 256 + threadIdx.x;
    const int row  = gtid >> 5;          // b*C + c
    const int lane = gtid & 31;          // s

    const float4* r4 = g_part4 + ((size_t)row * S_ + lane) * 2;
    float4 a  = __ldg(r4);
    float4 bq = __ldg(r4 + 1);

    float mn0 = a.x, mn1 = a.y, mn2 = a.z;
    float mx0 = a.w, mx1 = bq.x, mx2 = bq.y;

#pragma unroll
    for (int off = 16; off > 0; off >>= 1) {
        float b0 = __shfl_xor_sync(0xffffffffu, mn0, off);
        float b1 = __shfl_xor_sync(0xffffffffu, mn1, off);
        float b2 = __shfl_xor_sync(0xffffffffu, mn2, off);
        float c0 = __shfl_xor_sync(0xffffffffu, mx0, off);
        float c1 = __shfl_xor_sync(0xffffffffu, mx1, off);
        float c2 = __shfl_xor_sync(0xffffffffu, mx2, off);

        // merge two ascending triples -> 3 smallest of union
        {
            float x0 = fminf(mn0, b0), y0 = fmaxf(mn0, b0);
            float x1 = fminf(mn1, b1);
            float x2 = fminf(mn2, b2);
            mn0 = x0;
            mn1 = fminf(y0, x1);
            mn2 = fminf(x2, fmaxf(x1, y0));
        }
        // merge two descending triples -> 3 largest of union
        {
            float x0 = fmaxf(mx0, c0), y0 = fminf(mx0, c0);
            float x1 = fmaxf(mx1, c1);
            float x2 = fmaxf(mx2, c2);
            mx0 = x0;
            mx1 = fmaxf(y0, x1);
            mx2 = fmaxf(x2, fminf(x1, y0));
        }
    }

    if (lane == 0) {
        float* r = out + (size_t)row * 6;
        r[0] = mn0; r[1] = mn1; r[2] = mn2;
        r[3] = mx0; r[4] = mx1; r[5] = mx2;
    }
}

extern "C" void kernel_launch(void* const* d_in, const int* in_sizes, int n_in,
                              void* d_out, int out_size) {
    const float* x = (const float*)d_in[0];
    float* out = (float*)d_out;

    dim3 grid1(S_, B_);
    kmm_partial<<<grid1, C_>>>(x);

    // 8192 rows * 32 lanes = 262144 threads = 1024 blocks x 256
    kmm_reduce<<<(B_ * C_ * 32) / 256, 256>>>(out);
}